// round 1
// baseline (speedup 1.0000x reference)
#include <cuda_runtime.h>
#include <math.h>

#define B_ 4
#define S_ 2048
#define DM_ 512
#define H_ 8
#define D_ 64
#define LEFT_ 128
#define RIGHT_ 128

// Scratch (device globals: allocation-free rule)
__device__ float g_Q[B_ * S_ * DM_];
__device__ float g_K[B_ * S_ * DM_];
__device__ float g_V[B_ * S_ * DM_];
__device__ float g_ctx[B_ * S_ * DM_];
__device__ float g_vmean[B_ * H_ * D_];

// ---------------------------------------------------------------------------
// Tiled fp32 GEMM + bias: C[M,N] = A[M,K] @ W[K,N] + bias[N]
// BM=BN=128, BK=16, 256 threads, 8x8 per thread.
// ---------------------------------------------------------------------------
__global__ __launch_bounds__(256) void sgemm_bias(
    const float* __restrict__ A, const float* __restrict__ W,
    const float* __restrict__ bias, float* __restrict__ C,
    int M, int N, int K)
{
    __shared__ float As[16][128];
    __shared__ float Bs[16][128];
    const int bm = blockIdx.y * 128;
    const int bn = blockIdx.x * 128;
    const int tid = threadIdx.x;
    const int tx = tid & 15, ty = tid >> 4;

    float acc[8][8] = {};
    for (int k0 = 0; k0 < K; k0 += 16) {
        #pragma unroll
        for (int l = 0; l < 2; l++) {
            int v = tid + l * 256;
            int ar = v >> 2, ac = (v & 3) << 2;
            float4 a4 = *reinterpret_cast<const float4*>(&A[(bm + ar) * K + k0 + ac]);
            As[ac + 0][ar] = a4.x; As[ac + 1][ar] = a4.y;
            As[ac + 2][ar] = a4.z; As[ac + 3][ar] = a4.w;
            int br = v >> 5, bc = (v & 31) << 2;
            *reinterpret_cast<float4*>(&Bs[br][bc]) =
                *reinterpret_cast<const float4*>(&W[(k0 + br) * N + bn + bc]);
        }
        __syncthreads();
        #pragma unroll
        for (int kk = 0; kk < 16; kk++) {
            float a[8], bf[8];
            #pragma unroll
            for (int i = 0; i < 8; i++) a[i] = As[kk][ty * 8 + i];
            #pragma unroll
            for (int j = 0; j < 8; j++) bf[j] = Bs[kk][tx * 8 + j];
            #pragma unroll
            for (int i = 0; i < 8; i++)
                #pragma unroll
                for (int j = 0; j < 8; j++)
                    acc[i][j] += a[i] * bf[j];
        }
        __syncthreads();
    }
    #pragma unroll
    for (int i = 0; i < 8; i++) {
        int row = bm + ty * 8 + i;
        #pragma unroll
        for (int j = 0; j < 8; j += 4) {
            int col = bn + tx * 8 + j;
            float4 bb = *reinterpret_cast<const float4*>(&bias[col]);
            float4 o;
            o.x = acc[i][j + 0] + bb.x;
            o.y = acc[i][j + 1] + bb.y;
            o.z = acc[i][j + 2] + bb.z;
            o.w = acc[i][j + 3] + bb.w;
            *reinterpret_cast<float4*>(&C[row * N + col]) = o;
        }
    }
}

// ---------------------------------------------------------------------------
// Per-(b,h) mean of V over all S keys (needed for fully-masked query rows:
// in fp32, energy - 1e30 == -1e30 exactly for ALL keys -> uniform softmax
// over all 2048 keys -> ctx = mean(V)).
// ---------------------------------------------------------------------------
__global__ void vmean_kernel()
{
    int bh = blockIdx.x;          // 0 .. B*H-1
    int b = bh / H_, h = bh % H_;
    int d = threadIdx.x;          // 0..63
    float s = 0.f;
    #pragma unroll 8
    for (int j = 0; j < S_; j++)
        s += g_V[(b * S_ + j) * DM_ + h * D_ + d];
    g_vmean[bh * D_ + d] = s * (1.0f / S_);
}

// ---------------------------------------------------------------------------
// Banded attention: one block per (b, h, 64-query tile).
// Band boundaries for a 64-query tile are multiples of 64, so KT (key count)
// is always a multiple of 64 (192..320) and all keys are in [0, S).
// ---------------------------------------------------------------------------
#define SQ_STR 65
#define SKV_STR 65
#define SS_STR 321
#define ATTN_SMEM_BYTES ((64 * SQ_STR + 64 * SS_STR + 64 * SKV_STR) * 4)

__global__ __launch_bounds__(256) void attn_kernel(const int* __restrict__ x_len)
{
    const int q0 = blockIdx.x * 64;
    const int h  = blockIdx.y;
    const int b  = blockIdx.z;
    const int tid = threadIdx.x;
    const int tx = tid & 15, ty = tid >> 4;
    const int xlen = x_len[b];

    extern __shared__ float sm[];
    float* sQ  = sm;                       // 64 x 65
    float* sS  = sQ + 64 * SQ_STR;         // 64 x 321 (scores/probs)
    float* sKV = sS + 64 * SS_STR;         // 64 x 65 (K or V chunk)
    __shared__ int sEmpty[64];

    const int j_lo = max(0, q0 - LEFT_);
    const int j_hi = min(S_ - 1, q0 + 63 + RIGHT_);
    const int KT = j_hi - j_lo + 1;        // multiple of 64
    const int NC = KT >> 6;

    // Load Q tile [64 x 64]
    #pragma unroll
    for (int l = 0; l < 4; l++) {
        int v = tid + l * 256;
        int r = v >> 4, c4 = (v & 15) << 2;
        float4 q4 = *reinterpret_cast<const float4*>(
            &g_Q[(b * S_ + q0 + r) * DM_ + h * D_ + c4]);
        float* dst = &sQ[r * SQ_STR + c4];
        dst[0] = q4.x; dst[1] = q4.y; dst[2] = q4.z; dst[3] = q4.w;
    }

    // Scores: S = Q @ K^T / 8, in 64-key chunks
    for (int c = 0; c < NC; c++) {
        #pragma unroll
        for (int l = 0; l < 4; l++) {
            int v = tid + l * 256;
            int r = v >> 4, c4 = (v & 15) << 2;
            int j = j_lo + c * 64 + r;
            float4 k4 = *reinterpret_cast<const float4*>(
                &g_K[(b * S_ + j) * DM_ + h * D_ + c4]);
            float* dst = &sKV[r * SKV_STR + c4];
            dst[0] = k4.x; dst[1] = k4.y; dst[2] = k4.z; dst[3] = k4.w;
        }
        __syncthreads();
        float acc[4][4] = {};
        #pragma unroll 8
        for (int d = 0; d < 64; d++) {
            float a[4], kk[4];
            #pragma unroll
            for (int i = 0; i < 4; i++) a[i] = sQ[(ty * 4 + i) * SQ_STR + d];
            #pragma unroll
            for (int j = 0; j < 4; j++) kk[j] = sKV[(tx * 4 + j) * SKV_STR + d];
            #pragma unroll
            for (int i = 0; i < 4; i++)
                #pragma unroll
                for (int j = 0; j < 4; j++)
                    acc[i][j] += a[i] * kk[j];
        }
        #pragma unroll
        for (int i = 0; i < 4; i++)
            #pragma unroll
            for (int j = 0; j < 4; j++)
                sS[(ty * 4 + i) * SS_STR + c * 64 + tx * 4 + j] = acc[i][j] * 0.125f;
        __syncthreads();
    }

    // Softmax per query row (mask: band AND j < xlen). One thread per row.
    if (tid < 64) {
        int r = tid, iq = q0 + r;
        int lo = max(0, iq - LEFT_);
        int hi = min(S_ - 1, iq + RIGHT_);
        int vh = min(hi, xlen - 1);
        float* row = &sS[r * SS_STR];
        int llo = lo - j_lo, lhi = vh - j_lo;
        if (lhi < llo) {
            // no valid keys -> uniform over ALL S keys (handled via vmean)
            sEmpty[r] = 1;
            for (int k = 0; k < KT; k++) row[k] = 0.f;
        } else {
            sEmpty[r] = 0;
            float mx = -3.4e38f;
            for (int k = llo; k <= lhi; k++) mx = fmaxf(mx, row[k]);
            float sum = 0.f;
            for (int k = llo; k <= lhi; k++) {
                float e = __expf(row[k] - mx);
                row[k] = e; sum += e;
            }
            float inv = 1.0f / sum;
            for (int k = 0; k < KT; k++)
                row[k] = (k >= llo && k <= lhi) ? row[k] * inv : 0.f;
        }
    }
    __syncthreads();

    // ctx = P @ V, in 64-key chunks
    float acc2[4][4] = {};
    for (int c = 0; c < NC; c++) {
        #pragma unroll
        for (int l = 0; l < 4; l++) {
            int v = tid + l * 256;
            int r = v >> 4, c4 = (v & 15) << 2;
            int j = j_lo + c * 64 + r;
            float4 v4 = *reinterpret_cast<const float4*>(
                &g_V[(b * S_ + j) * DM_ + h * D_ + c4]);
            float* dst = &sKV[r * SKV_STR + c4];
            dst[0] = v4.x; dst[1] = v4.y; dst[2] = v4.z; dst[3] = v4.w;
        }
        __syncthreads();
        #pragma unroll 8
        for (int kk = 0; kk < 64; kk++) {
            float a[4], vv[4];
            #pragma unroll
            for (int i = 0; i < 4; i++) a[i] = sS[(ty * 4 + i) * SS_STR + c * 64 + kk];
            #pragma unroll
            for (int j = 0; j < 4; j++) vv[j] = sKV[kk * SKV_STR + tx * 4 + j];
            #pragma unroll
            for (int i = 0; i < 4; i++)
                #pragma unroll
                for (int j = 0; j < 4; j++)
                    acc2[i][j] += a[i] * vv[j];
        }
        __syncthreads();
    }

    // Write ctx [B,S,H*D]; empty rows get mean(V)
    #pragma unroll
    for (int i = 0; i < 4; i++) {
        int r = ty * 4 + i, q = q0 + r;
        #pragma unroll
        for (int j = 0; j < 4; j++) {
            int d = tx * 4 + j;
            float addv = sEmpty[r] ? g_vmean[(b * H_ + h) * D_ + d] : 0.f;
            g_ctx[(b * S_ + q) * DM_ + h * D_ + d] = acc2[i][j] + addv;
        }
    }
}

// ---------------------------------------------------------------------------
extern "C" void kernel_launch(void* const* d_in, const int* in_sizes, int n_in,
                              void* d_out, int out_size)
{
    const float* x  = (const float*)d_in[0];
    const float* Wq = (const float*)d_in[1];
    const float* bq = (const float*)d_in[2];
    const float* Wk = (const float*)d_in[3];
    const float* bk = (const float*)d_in[4];
    const float* Wv = (const float*)d_in[5];
    const float* bv = (const float*)d_in[6];
    const float* Wo = (const float*)d_in[7];
    const float* bo = (const float*)d_in[8];
    const int* xlen = (const int*)d_in[9];
    float* out = (float*)d_out;

    void *pQ, *pK, *pV, *pC;
    cudaGetSymbolAddress(&pQ, g_Q);
    cudaGetSymbolAddress(&pK, g_K);
    cudaGetSymbolAddress(&pV, g_V);
    cudaGetSymbolAddress(&pC, g_ctx);

    const int M = B_ * S_;
    dim3 gg(DM_ / 128, M / 128);

    sgemm_bias<<<gg, 256>>>(x, Wq, bq, (float*)pQ, M, DM_, DM_);
    sgemm_bias<<<gg, 256>>>(x, Wk, bk, (float*)pK, M, DM_, DM_);
    sgemm_bias<<<gg, 256>>>(x, Wv, bv, (float*)pV, M, DM_, DM_);

    vmean_kernel<<<B_ * H_, 64>>>();

    cudaFuncSetAttribute(attn_kernel,
                         cudaFuncAttributeMaxDynamicSharedMemorySize,
                         ATTN_SMEM_BYTES);
    attn_kernel<<<dim3(S_ / 64, H_, B_), 256, ATTN_SMEM_BYTES>>>(xlen);

    sgemm_bias<<<gg, 256>>>((const float*)pC, Wo, bo, out, M, DM_, DM_);
}

// round 3
// speedup vs baseline: 1.1738x; 1.1738x over previous
#include <cuda_runtime.h>
#include <math.h>

#define B_ 4
#define S_ 2048
#define DM_ 512
#define H_ 8
#define D_ 64
#define LEFT_ 128
#define RIGHT_ 128

// Scratch (device globals: allocation-free rule)
__device__ float g_Q[B_ * S_ * DM_];
__device__ float g_K[B_ * S_ * DM_];
__device__ float g_V[B_ * S_ * DM_];
__device__ float g_ctx[B_ * S_ * DM_];
__device__ float g_vmean[B_ * H_ * D_];

// ---------------------------------------------------------------------------
// Double-buffered fp32 GEMM + bias: C[M,N] = A[M,K] @ W[K,N] + bias[N]
// BM=BN=128, BK=16, 256 threads, 8x8 per thread, ping-pong smem.
// ---------------------------------------------------------------------------
__device__ __forceinline__ void sgemm_body(
    const float* __restrict__ A, const float* __restrict__ W,
    const float* __restrict__ bias, float* __restrict__ C,
    int M, int N, int K, int bm, int bn,
    float (*As)[16][128], float (*Bs)[16][128])
{
    const int tid = threadIdx.x;
    const int tx = tid & 15, ty = tid >> 4;

    // Loader index precompute (two float4 per thread per operand)
    const int a0r = tid >> 2,          a0c = (tid & 3) << 2;
    const int a1r = (tid + 256) >> 2,  a1c = ((tid + 256) & 3) << 2;
    const int b0r = tid >> 5,          b0c = (tid & 31) << 2;
    const int b1r = (tid + 256) >> 5,  b1c = ((tid + 256) & 31) << 2;

    // Prologue: load tile 0 into buffer 0
    {
        float4 a0 = *reinterpret_cast<const float4*>(&A[(bm + a0r) * K + a0c]);
        float4 a1 = *reinterpret_cast<const float4*>(&A[(bm + a1r) * K + a1c]);
        float4 b0 = *reinterpret_cast<const float4*>(&W[b0r * N + bn + b0c]);
        float4 b1 = *reinterpret_cast<const float4*>(&W[b1r * N + bn + b1c]);
        As[0][a0c + 0][a0r] = a0.x; As[0][a0c + 1][a0r] = a0.y;
        As[0][a0c + 2][a0r] = a0.z; As[0][a0c + 3][a0r] = a0.w;
        As[0][a1c + 0][a1r] = a1.x; As[0][a1c + 1][a1r] = a1.y;
        As[0][a1c + 2][a1r] = a1.z; As[0][a1c + 3][a1r] = a1.w;
        *reinterpret_cast<float4*>(&Bs[0][b0r][b0c]) = b0;
        *reinterpret_cast<float4*>(&Bs[0][b1r][b1c]) = b1;
    }
    __syncthreads();

    float acc[8][8] = {};
    const int T = K >> 4;
    for (int t = 0; t < T; t++) {
        const int buf = t & 1;
        float4 na0, na1, nb0, nb1;
        const bool has_next = (t + 1 < T);
        if (has_next) {
            int k0 = (t + 1) << 4;
            na0 = *reinterpret_cast<const float4*>(&A[(bm + a0r) * K + k0 + a0c]);
            na1 = *reinterpret_cast<const float4*>(&A[(bm + a1r) * K + k0 + a1c]);
            nb0 = *reinterpret_cast<const float4*>(&W[(k0 + b0r) * N + bn + b0c]);
            nb1 = *reinterpret_cast<const float4*>(&W[(k0 + b1r) * N + bn + b1c]);
        }
        #pragma unroll
        for (int kk = 0; kk < 16; kk++) {
            float a[8], bf[8];
            #pragma unroll
            for (int i = 0; i < 8; i++) a[i] = As[buf][kk][ty * 8 + i];
            #pragma unroll
            for (int j = 0; j < 8; j++) bf[j] = Bs[buf][kk][tx * 8 + j];
            #pragma unroll
            for (int i = 0; i < 8; i++)
                #pragma unroll
                for (int j = 0; j < 8; j++)
                    acc[i][j] += a[i] * bf[j];
        }
        if (has_next) {
            const int nb = buf ^ 1;
            As[nb][a0c + 0][a0r] = na0.x; As[nb][a0c + 1][a0r] = na0.y;
            As[nb][a0c + 2][a0r] = na0.z; As[nb][a0c + 3][a0r] = na0.w;
            As[nb][a1c + 0][a1r] = na1.x; As[nb][a1c + 1][a1r] = na1.y;
            As[nb][a1c + 2][a1r] = na1.z; As[nb][a1c + 3][a1r] = na1.w;
            *reinterpret_cast<float4*>(&Bs[nb][b0r][b0c]) = nb0;
            *reinterpret_cast<float4*>(&Bs[nb][b1r][b1c]) = nb1;
            __syncthreads();
        }
    }

    #pragma unroll
    for (int i = 0; i < 8; i++) {
        int row = bm + ty * 8 + i;
        #pragma unroll
        for (int j = 0; j < 8; j += 4) {
            int col = bn + tx * 8 + j;
            float4 bb = *reinterpret_cast<const float4*>(&bias[col]);
            float4 o;
            o.x = acc[i][j + 0] + bb.x;
            o.y = acc[i][j + 1] + bb.y;
            o.z = acc[i][j + 2] + bb.z;
            o.w = acc[i][j + 3] + bb.w;
            *reinterpret_cast<float4*>(&C[row * N + col]) = o;
        }
    }
}

// Fused Q/K/V projection: blockIdx.z selects which weight/output.
__global__ __launch_bounds__(256) void qkv_gemm(
    const float* __restrict__ x,
    const float* __restrict__ Wq, const float* __restrict__ bq,
    const float* __restrict__ Wk, const float* __restrict__ bk,
    const float* __restrict__ Wv, const float* __restrict__ bv)
{
    __shared__ float As[2][16][128];
    __shared__ float Bs[2][16][128];
    const float* W; const float* bias; float* C;
    if (blockIdx.z == 0)      { W = Wq; bias = bq; C = g_Q; }
    else if (blockIdx.z == 1) { W = Wk; bias = bk; C = g_K; }
    else                      { W = Wv; bias = bv; C = g_V; }
    sgemm_body(x, W, bias, C, B_ * S_, DM_, DM_,
               blockIdx.y * 128, blockIdx.x * 128, As, Bs);
}

__global__ __launch_bounds__(256) void out_gemm(
    const float* __restrict__ Wo, const float* __restrict__ bo,
    float* __restrict__ out)
{
    __shared__ float As[2][16][128];
    __shared__ float Bs[2][16][128];
    sgemm_body(g_ctx, Wo, bo, out, B_ * S_, DM_, DM_,
               blockIdx.y * 128, blockIdx.x * 128, As, Bs);
}

// ---------------------------------------------------------------------------
// Per-(b,h) mean of V over all S keys — parallel version.
// One block per (b,h): 512 threads = 8 j-chunks x 64 dims.
// ---------------------------------------------------------------------------
__global__ __launch_bounds__(512) void vmean_kernel()
{
    __shared__ float red[8][64];
    const int bh = blockIdx.x;
    const int b = bh / H_, h = bh % H_;
    const int d = threadIdx.x & 63;
    const int c = threadIdx.x >> 6;   // 0..7
    float s = 0.f;
    const int j0 = c * (S_ / 8);
    #pragma unroll 4
    for (int j = j0; j < j0 + S_ / 8; j++)
        s += g_V[(b * S_ + j) * DM_ + h * D_ + d];
    red[c][d] = s;
    __syncthreads();
    if (c == 0) {
        float t = 0.f;
        #pragma unroll
        for (int k = 0; k < 8; k++) t += red[k][d];
        g_vmean[bh * D_ + d] = t * (1.0f / S_);
    }
}

// ---------------------------------------------------------------------------
// Banded attention: one block per (b, h, 64-query tile).
// ---------------------------------------------------------------------------
#define SQ_STR 65
#define SKV_STR 65
#define SS_STR 321
#define ATTN_SMEM_BYTES ((64 * SQ_STR + 64 * SS_STR + 64 * SKV_STR) * 4)

__global__ __launch_bounds__(256) void attn_kernel(const int* __restrict__ x_len)
{
    const int q0 = blockIdx.x * 64;
    const int h  = blockIdx.y;
    const int b  = blockIdx.z;
    const int tid = threadIdx.x;
    const int tx = tid & 15, ty = tid >> 4;
    const int wid = tid >> 5, lane = tid & 31;
    const int xlen = x_len[b];

    extern __shared__ float sm[];
    float* sQ  = sm;                       // 64 x 65
    float* sS  = sQ + 64 * SQ_STR;         // 64 x 321 (scores/probs)
    float* sKV = sS + 64 * SS_STR;         // 64 x 65 (K or V chunk)
    __shared__ int sEmpty[64];

    const int j_lo = max(0, q0 - LEFT_);
    const int j_hi = min(S_ - 1, q0 + 63 + RIGHT_);
    const int KT = j_hi - j_lo + 1;        // multiple of 64
    const int NC = KT >> 6;

    // Load Q tile [64 x 64]
    #pragma unroll
    for (int l = 0; l < 4; l++) {
        int v = tid + l * 256;
        int r = v >> 4, c4 = (v & 15) << 2;
        float4 q4 = *reinterpret_cast<const float4*>(
            &g_Q[(b * S_ + q0 + r) * DM_ + h * D_ + c4]);
        float* dst = &sQ[r * SQ_STR + c4];
        dst[0] = q4.x; dst[1] = q4.y; dst[2] = q4.z; dst[3] = q4.w;
    }

    // Scores: S = Q @ K^T / 8, in 64-key chunks
    for (int c = 0; c < NC; c++) {
        #pragma unroll
        for (int l = 0; l < 4; l++) {
            int v = tid + l * 256;
            int r = v >> 4, c4 = (v & 15) << 2;
            int j = j_lo + c * 64 + r;
            float4 k4 = *reinterpret_cast<const float4*>(
                &g_K[(b * S_ + j) * DM_ + h * D_ + c4]);
            float* dst = &sKV[r * SKV_STR + c4];
            dst[0] = k4.x; dst[1] = k4.y; dst[2] = k4.z; dst[3] = k4.w;
        }
        __syncthreads();
        float acc[4][4] = {};
        #pragma unroll 8
        for (int d = 0; d < 64; d++) {
            float a[4], kk[4];
            #pragma unroll
            for (int i = 0; i < 4; i++) a[i] = sQ[(ty * 4 + i) * SQ_STR + d];
            #pragma unroll
            for (int j = 0; j < 4; j++) kk[j] = sKV[(tx * 4 + j) * SKV_STR + d];
            #pragma unroll
            for (int i = 0; i < 4; i++)
                #pragma unroll
                for (int j = 0; j < 4; j++)
                    acc[i][j] += a[i] * kk[j];
        }
        #pragma unroll
        for (int i = 0; i < 4; i++)
            #pragma unroll
            for (int j = 0; j < 4; j++)
                sS[(ty * 4 + i) * SS_STR + c * 64 + tx * 4 + j] = acc[i][j] * 0.125f;
        __syncthreads();
    }

    // Softmax: one warp per query row (8 warps x 8 rows each).
    for (int r = wid; r < 64; r += 8) {
        int iq = q0 + r;
        int lo = max(0, iq - LEFT_);
        int hi = min(S_ - 1, iq + RIGHT_);
        int vh = min(hi, xlen - 1);
        float* row = &sS[r * SS_STR];
        int llo = lo - j_lo, lhi = vh - j_lo;
        if (lhi < llo) {
            // no valid keys -> uniform over ALL S keys (handled via vmean)
            if (lane == 0) sEmpty[r] = 1;
            for (int k = lane; k < KT; k += 32) row[k] = 0.f;
        } else {
            if (lane == 0) sEmpty[r] = 0;
            float mx = -3.4e38f;
            for (int k = llo + lane; k <= lhi; k += 32) mx = fmaxf(mx, row[k]);
            #pragma unroll
            for (int o = 16; o; o >>= 1) mx = fmaxf(mx, __shfl_xor_sync(~0u, mx, o));
            float sum = 0.f;
            for (int k = llo + lane; k <= lhi; k += 32) {
                float e = __expf(row[k] - mx);
                row[k] = e; sum += e;
            }
            #pragma unroll
            for (int o = 16; o; o >>= 1) sum += __shfl_xor_sync(~0u, sum, o);
            float inv = 1.0f / sum;
            __syncwarp();
            for (int k = lane; k < KT; k += 32)
                row[k] = (k >= llo && k <= lhi) ? row[k] * inv : 0.f;
        }
    }
    __syncthreads();

    // ctx = P @ V, in 64-key chunks
    float acc2[4][4] = {};
    for (int c = 0; c < NC; c++) {
        #pragma unroll
        for (int l = 0; l < 4; l++) {
            int v = tid + l * 256;
            int r = v >> 4, c4 = (v & 15) << 2;
            int j = j_lo + c * 64 + r;
            float4 v4 = *reinterpret_cast<const float4*>(
                &g_V[(b * S_ + j) * DM_ + h * D_ + c4]);
            float* dst = &sKV[r * SKV_STR + c4];
            dst[0] = v4.x; dst[1] = v4.y; dst[2] = v4.z; dst[3] = v4.w;
        }
        __syncthreads();
        #pragma unroll 8
        for (int kk = 0; kk < 64; kk++) {
            float a[4], vv[4];
            #pragma unroll
            for (int i = 0; i < 4; i++) a[i] = sS[(ty * 4 + i) * SS_STR + c * 64 + kk];
            #pragma unroll
            for (int j = 0; j < 4; j++) vv[j] = sKV[kk * SKV_STR + tx * 4 + j];
            #pragma unroll
            for (int i = 0; i < 4; i++)
                #pragma unroll
                for (int j = 0; j < 4; j++)
                    acc2[i][j] += a[i] * vv[j];
        }
        __syncthreads();
    }

    // Write ctx [B,S,H*D]; empty rows get mean(V)
    #pragma unroll
    for (int i = 0; i < 4; i++) {
        int r = ty * 4 + i, q = q0 + r;
        #pragma unroll
        for (int j = 0; j < 4; j++) {
            int d = tx * 4 + j;
            float addv = sEmpty[r] ? g_vmean[(b * H_ + h) * D_ + d] : 0.f;
            g_ctx[(b * S_ + q) * DM_ + h * D_ + d] = acc2[i][j] + addv;
        }
    }
}

// ---------------------------------------------------------------------------
extern "C" void kernel_launch(void* const* d_in, const int* in_sizes, int n_in,
                              void* d_out, int out_size)
{
    const float* x  = (const float*)d_in[0];
    const float* Wq = (const float*)d_in[1];
    const float* bq = (const float*)d_in[2];
    const float* Wk = (const float*)d_in[3];
    const float* bk = (const float*)d_in[4];
    const float* Wv = (const float*)d_in[5];
    const float* bv = (const float*)d_in[6];
    const float* Wo = (const float*)d_in[7];
    const float* bo = (const float*)d_in[8];
    const int* xlen = (const int*)d_in[9];
    float* out = (float*)d_out;

    const int M = B_ * S_;
    dim3 gqkv(DM_ / 128, M / 128, 3);
    dim3 go(DM_ / 128, M / 128);

    qkv_gemm<<<gqkv, 256>>>(x, Wq, bq, Wk, bk, Wv, bv);

    vmean_kernel<<<B_ * H_, 512>>>();

    cudaFuncSetAttribute(attn_kernel,
                         cudaFuncAttributeMaxDynamicSharedMemorySize,
                         ATTN_SMEM_BYTES);
    attn_kernel<<<dim3(S_ / 64, H_, B_), 256, ATTN_SMEM_BYTES>>>(xlen);

    out_gemm<<<go, 256>>>(Wo, bo, out);
}

// round 5
// speedup vs baseline: 1.6218x; 1.3816x over previous
#include <cuda_runtime.h>
#include <cuda_bf16.h>
#include <cstdint>
#include <math.h>

#define B_ 4
#define S_ 2048
#define DM_ 512
#define H_ 8
#define D_ 64
#define LEFT_ 128
#define RIGHT_ 128

// Scratch (device globals: allocation-free rule)
__device__ float g_Q[B_ * S_ * DM_];
__device__ float g_K[B_ * S_ * DM_];
__device__ float g_V[B_ * S_ * DM_];
__device__ float g_ctx[B_ * S_ * DM_];
__device__ float g_vmean[B_ * H_ * D_];

// ===========================================================================
// bf16x3-split GEMM on mma.sync (legacy HMMA, generic sm_103 target).
// C[M,512] = A[M,512] @ W[512,512] + bias. CTA tile 128x128, warp tile 32x64,
// K-chunks of 32, double-buffered smem, W transposed to [n][k] during convert.
// ===========================================================================
#define KCH 32
#define KSTRB 80                 // smem row stride in bytes (40 bf16)
#define ABUF 10240               // 128 rows * 80 B
#define BUFSZ (4 * ABUF)         // Ah, Al, Bh, Bl
#define GEMM_SMEM_BYTES (2 * BUFSZ)   // 81920

__device__ __forceinline__ void bf16_split(float x0, float x1,
                                           uint32_t& hi, uint32_t& lo) {
    __nv_bfloat162 h = __float22bfloat162_rn(make_float2(x0, x1));
    float2 f = __bfloat1622float2(h);
    __nv_bfloat162 l = __float22bfloat162_rn(make_float2(x0 - f.x, x1 - f.y));
    hi = *reinterpret_cast<uint32_t*>(&h);
    lo = *reinterpret_cast<uint32_t*>(&l);
}

__device__ __forceinline__ void mma_bf16(float* c, const uint32_t* a,
                                         const uint32_t* b) {
    asm volatile(
        "mma.sync.aligned.m16n8k16.row.col.f32.bf16.bf16.f32 "
        "{%0,%1,%2,%3}, {%4,%5,%6,%7}, {%8,%9}, {%0,%1,%2,%3};"
        : "+f"(c[0]), "+f"(c[1]), "+f"(c[2]), "+f"(c[3])
        : "r"(a[0]), "r"(a[1]), "r"(a[2]), "r"(a[3]), "r"(b[0]), "r"(b[1]));
}

// Convert staged fp32 regs -> bf16 hi/lo tiles in smem buffer `base`.
__device__ __forceinline__ void sts_chunk(char* base,
    const float4* sa, const float4* sb,
    int arow, int akq, int bkr, int bn4)
{
    char* pAh = base;
    char* pAl = base + ABUF;
    char* pBh = base + 2 * ABUF;
    char* pBl = base + 3 * ABUF;
    #pragma unroll
    for (int i = 0; i < 4; i++) {
        uint32_t h0, l0, h1, l1;
        bf16_split(sa[i].x, sa[i].y, h0, l0);
        bf16_split(sa[i].z, sa[i].w, h1, l1);
        int off = arow * KSTRB + (akq + i * 4) * 2;
        *reinterpret_cast<uint2*>(pAh + off) = make_uint2(h0, h1);
        *reinterpret_cast<uint2*>(pAl + off) = make_uint2(l0, l1);
    }
    #pragma unroll
    for (int m = 0; m < 4; m++) {
        float v0 = reinterpret_cast<const float*>(&sb[0])[m];
        float v1 = reinterpret_cast<const float*>(&sb[1])[m];
        float v2 = reinterpret_cast<const float*>(&sb[2])[m];
        float v3 = reinterpret_cast<const float*>(&sb[3])[m];
        uint32_t h0, l0, h1, l1;
        bf16_split(v0, v1, h0, l0);
        bf16_split(v2, v3, h1, l1);
        int off = (bn4 + m) * KSTRB + bkr * 8;
        *reinterpret_cast<uint2*>(pBh + off) = make_uint2(h0, h1);
        *reinterpret_cast<uint2*>(pBl + off) = make_uint2(l0, l1);
    }
}

__device__ __forceinline__ void gemm_mma_body(
    const float* __restrict__ A, const float* __restrict__ W,
    const float* __restrict__ bias, float* __restrict__ C,
    int bm, int bn)
{
    extern __shared__ char smc[];
    const int tid = threadIdx.x;
    const int wid = tid >> 5, lane = tid & 31;
    const int g = lane >> 2, tg = lane & 3;
    const int wm = (wid & 3) * 32, wn = (wid >> 2) * 64;

    // Loader indices
    const int arow = tid >> 1, akq = (tid & 1) * 16;
    const int bkr = wid, bn4 = lane * 4;

    float acc[2][8][4] = {};
    float4 sa[4], sb[4];

    // Prologue: stage chunk 0
    #pragma unroll
    for (int i = 0; i < 4; i++)
        sa[i] = *reinterpret_cast<const float4*>(&A[(bm + arow) * DM_ + akq + i * 4]);
    #pragma unroll
    for (int j = 0; j < 4; j++)
        sb[j] = *reinterpret_cast<const float4*>(&W[(bkr * 4 + j) * DM_ + bn + bn4]);
    sts_chunk(smc, sa, sb, arow, akq, bkr, bn4);
    __syncthreads();

    for (int c = 0; c < DM_ / KCH; c++) {
        const int buf = c & 1;
        const bool has_next = (c + 1 < DM_ / KCH);
        if (has_next) {
            const int k0 = (c + 1) * KCH;
            #pragma unroll
            for (int i = 0; i < 4; i++)
                sa[i] = *reinterpret_cast<const float4*>(
                    &A[(bm + arow) * DM_ + k0 + akq + i * 4]);
            #pragma unroll
            for (int j = 0; j < 4; j++)
                sb[j] = *reinterpret_cast<const float4*>(
                    &W[(k0 + bkr * 4 + j) * DM_ + bn + bn4]);
        }

        char* pAh = smc + buf * BUFSZ;
        char* pAl = pAh + ABUF;
        char* pBh = pAh + 2 * ABUF;
        char* pBl = pAh + 3 * ABUF;

        #pragma unroll
        for (int ks = 0; ks < 2; ks++) {
            const int kb = (ks * 16 + tg * 2) * 2;
            uint32_t Ah[2][4], Al[2][4];
            #pragma unroll
            for (int mt = 0; mt < 2; mt++) {
                const int r0 = wm + mt * 16 + g;
                Ah[mt][0] = *reinterpret_cast<uint32_t*>(pAh + r0 * KSTRB + kb);
                Ah[mt][1] = *reinterpret_cast<uint32_t*>(pAh + (r0 + 8) * KSTRB + kb);
                Ah[mt][2] = *reinterpret_cast<uint32_t*>(pAh + r0 * KSTRB + kb + 16);
                Ah[mt][3] = *reinterpret_cast<uint32_t*>(pAh + (r0 + 8) * KSTRB + kb + 16);
                Al[mt][0] = *reinterpret_cast<uint32_t*>(pAl + r0 * KSTRB + kb);
                Al[mt][1] = *reinterpret_cast<uint32_t*>(pAl + (r0 + 8) * KSTRB + kb);
                Al[mt][2] = *reinterpret_cast<uint32_t*>(pAl + r0 * KSTRB + kb + 16);
                Al[mt][3] = *reinterpret_cast<uint32_t*>(pAl + (r0 + 8) * KSTRB + kb + 16);
            }
            #pragma unroll
            for (int nt = 0; nt < 8; nt++) {
                const int n = wn + nt * 8 + g;
                uint32_t Bh[2], Bl[2];
                Bh[0] = *reinterpret_cast<uint32_t*>(pBh + n * KSTRB + kb);
                Bh[1] = *reinterpret_cast<uint32_t*>(pBh + n * KSTRB + kb + 16);
                Bl[0] = *reinterpret_cast<uint32_t*>(pBl + n * KSTRB + kb);
                Bl[1] = *reinterpret_cast<uint32_t*>(pBl + n * KSTRB + kb + 16);
                #pragma unroll
                for (int mt = 0; mt < 2; mt++) {
                    mma_bf16(acc[mt][nt], Ah[mt], Bh);
                    mma_bf16(acc[mt][nt], Ah[mt], Bl);
                    mma_bf16(acc[mt][nt], Al[mt], Bh);
                }
            }
        }

        if (has_next) {
            sts_chunk(smc + (buf ^ 1) * BUFSZ, sa, sb, arow, akq, bkr, bn4);
            __syncthreads();
        }
    }

    // Epilogue: fragment -> gmem with bias
    #pragma unroll
    for (int mt = 0; mt < 2; mt++) {
        const int row0 = bm + wm + mt * 16 + g;
        #pragma unroll
        for (int nt = 0; nt < 8; nt++) {
            const int col = bn + wn + nt * 8 + tg * 2;
            float2 b2 = *reinterpret_cast<const float2*>(&bias[col]);
            float2 o0, o1;
            o0.x = acc[mt][nt][0] + b2.x;
            o0.y = acc[mt][nt][1] + b2.y;
            o1.x = acc[mt][nt][2] + b2.x;
            o1.y = acc[mt][nt][3] + b2.y;
            *reinterpret_cast<float2*>(&C[row0 * DM_ + col]) = o0;
            *reinterpret_cast<float2*>(&C[(row0 + 8) * DM_ + col]) = o1;
        }
    }
}

__global__ __launch_bounds__(256) void qkv_gemm_tc(
    const float* __restrict__ x,
    const float* __restrict__ Wq, const float* __restrict__ bq,
    const float* __restrict__ Wk, const float* __restrict__ bk,
    const float* __restrict__ Wv, const float* __restrict__ bv)
{
    const float* W; const float* bias; float* C;
    if (blockIdx.z == 0)      { W = Wq; bias = bq; C = g_Q; }
    else if (blockIdx.z == 1) { W = Wk; bias = bk; C = g_K; }
    else                      { W = Wv; bias = bv; C = g_V; }
    gemm_mma_body(x, W, bias, C, blockIdx.y * 128, blockIdx.x * 128);
}

__global__ __launch_bounds__(256) void out_gemm_tc(
    const float* __restrict__ Wo, const float* __restrict__ bo,
    float* __restrict__ out)
{
    gemm_mma_body(g_ctx, Wo, bo, out, blockIdx.y * 128, blockIdx.x * 128);
}

// ===========================================================================
// Per-(b,h) mean of V (for fully-masked rows: uniform softmax over all keys)
// ===========================================================================
__global__ __launch_bounds__(512) void vmean_kernel()
{
    __shared__ float red[8][64];
    const int bh = blockIdx.x;
    const int b = bh / H_, h = bh % H_;
    const int d = threadIdx.x & 63;
    const int c = threadIdx.x >> 6;
    float s = 0.f;
    const int j0 = c * (S_ / 8);
    #pragma unroll 4
    for (int j = j0; j < j0 + S_ / 8; j++)
        s += g_V[(b * S_ + j) * DM_ + h * D_ + d];
    red[c][d] = s;
    __syncthreads();
    if (c == 0) {
        float t = 0.f;
        #pragma unroll
        for (int k = 0; k < 8; k++) t += red[k][d];
        g_vmean[bh * D_ + d] = t * (1.0f / S_);
    }
}

// ===========================================================================
// Banded attention (unchanged from best passing version)
// ===========================================================================
#define SQ_STR 65
#define SKV_STR 65
#define SS_STR 321
#define ATTN_SMEM_BYTES ((64 * SQ_STR + 64 * SS_STR + 64 * SKV_STR) * 4)

__global__ __launch_bounds__(256) void attn_kernel(const int* __restrict__ x_len)
{
    const int q0 = blockIdx.x * 64;
    const int h  = blockIdx.y;
    const int b  = blockIdx.z;
    const int tid = threadIdx.x;
    const int tx = tid & 15, ty = tid >> 4;
    const int wid = tid >> 5, lane = tid & 31;
    const int xlen = x_len[b];

    extern __shared__ float sm[];
    float* sQ  = sm;
    float* sS  = sQ + 64 * SQ_STR;
    float* sKV = sS + 64 * SS_STR;
    __shared__ int sEmpty[64];

    const int j_lo = max(0, q0 - LEFT_);
    const int j_hi = min(S_ - 1, q0 + 63 + RIGHT_);
    const int KT = j_hi - j_lo + 1;
    const int NC = KT >> 6;

    #pragma unroll
    for (int l = 0; l < 4; l++) {
        int v = tid + l * 256;
        int r = v >> 4, c4 = (v & 15) << 2;
        float4 q4 = *reinterpret_cast<const float4*>(
            &g_Q[(b * S_ + q0 + r) * DM_ + h * D_ + c4]);
        float* dst = &sQ[r * SQ_STR + c4];
        dst[0] = q4.x; dst[1] = q4.y; dst[2] = q4.z; dst[3] = q4.w;
    }

    for (int c = 0; c < NC; c++) {
        #pragma unroll
        for (int l = 0; l < 4; l++) {
            int v = tid + l * 256;
            int r = v >> 4, c4 = (v & 15) << 2;
            int j = j_lo + c * 64 + r;
            float4 k4 = *reinterpret_cast<const float4*>(
                &g_K[(b * S_ + j) * DM_ + h * D_ + c4]);
            float* dst = &sKV[r * SKV_STR + c4];
            dst[0] = k4.x; dst[1] = k4.y; dst[2] = k4.z; dst[3] = k4.w;
        }
        __syncthreads();
        float acc[4][4] = {};
        #pragma unroll 8
        for (int d = 0; d < 64; d++) {
            float a[4], kk[4];
            #pragma unroll
            for (int i = 0; i < 4; i++) a[i] = sQ[(ty * 4 + i) * SQ_STR + d];
            #pragma unroll
            for (int j = 0; j < 4; j++) kk[j] = sKV[(tx * 4 + j) * SKV_STR + d];
            #pragma unroll
            for (int i = 0; i < 4; i++)
                #pragma unroll
                for (int j = 0; j < 4; j++)
                    acc[i][j] += a[i] * kk[j];
        }
        #pragma unroll
        for (int i = 0; i < 4; i++)
            #pragma unroll
            for (int j = 0; j < 4; j++)
                sS[(ty * 4 + i) * SS_STR + c * 64 + tx * 4 + j] = acc[i][j] * 0.125f;
        __syncthreads();
    }

    for (int r = wid; r < 64; r += 8) {
        int iq = q0 + r;
        int lo = max(0, iq - LEFT_);
        int hi = min(S_ - 1, iq + RIGHT_);
        int vh = min(hi, xlen - 1);
        float* row = &sS[r * SS_STR];
        int llo = lo - j_lo, lhi = vh - j_lo;
        if (lhi < llo) {
            if (lane == 0) sEmpty[r] = 1;
            for (int k = lane; k < KT; k += 32) row[k] = 0.f;
        } else {
            if (lane == 0) sEmpty[r] = 0;
            float mx = -3.4e38f;
            for (int k = llo + lane; k <= lhi; k += 32) mx = fmaxf(mx, row[k]);
            #pragma unroll
            for (int o = 16; o; o >>= 1) mx = fmaxf(mx, __shfl_xor_sync(~0u, mx, o));
            float sum = 0.f;
            for (int k = llo + lane; k <= lhi; k += 32) {
                float e = __expf(row[k] - mx);
                row[k] = e; sum += e;
            }
            #pragma unroll
            for (int o = 16; o; o >>= 1) sum += __shfl_xor_sync(~0u, sum, o);
            float inv = 1.0f / sum;
            __syncwarp();
            for (int k = lane; k < KT; k += 32)
                row[k] = (k >= llo && k <= lhi) ? row[k] * inv : 0.f;
        }
    }
    __syncthreads();

    float acc2[4][4] = {};
    for (int c = 0; c < NC; c++) {
        #pragma unroll
        for (int l = 0; l < 4; l++) {
            int v = tid + l * 256;
            int r = v >> 4, c4 = (v & 15) << 2;
            int j = j_lo + c * 64 + r;
            float4 v4 = *reinterpret_cast<const float4*>(
                &g_V[(b * S_ + j) * DM_ + h * D_ + c4]);
            float* dst = &sKV[r * SKV_STR + c4];
            dst[0] = v4.x; dst[1] = v4.y; dst[2] = v4.z; dst[3] = v4.w;
        }
        __syncthreads();
        #pragma unroll 8
        for (int kk = 0; kk < 64; kk++) {
            float a[4], vv[4];
            #pragma unroll
            for (int i = 0; i < 4; i++) a[i] = sS[(ty * 4 + i) * SS_STR + c * 64 + kk];
            #pragma unroll
            for (int j = 0; j < 4; j++) vv[j] = sKV[kk * SKV_STR + tx * 4 + j];
            #pragma unroll
            for (int i = 0; i < 4; i++)
                #pragma unroll
                for (int j = 0; j < 4; j++)
                    acc2[i][j] += a[i] * vv[j];
        }
        __syncthreads();
    }

    #pragma unroll
    for (int i = 0; i < 4; i++) {
        int r = ty * 4 + i, q = q0 + r;
        #pragma unroll
        for (int j = 0; j < 4; j++) {
            int d = tx * 4 + j;
            float addv = sEmpty[r] ? g_vmean[(b * H_ + h) * D_ + d] : 0.f;
            g_ctx[(b * S_ + q) * DM_ + h * D_ + d] = acc2[i][j] + addv;
        }
    }
}

// ---------------------------------------------------------------------------
extern "C" void kernel_launch(void* const* d_in, const int* in_sizes, int n_in,
                              void* d_out, int out_size)
{
    const float* x  = (const float*)d_in[0];
    const float* Wq = (const float*)d_in[1];
    const float* bq = (const float*)d_in[2];
    const float* Wk = (const float*)d_in[3];
    const float* bk = (const float*)d_in[4];
    const float* Wv = (const float*)d_in[5];
    const float* bv = (const float*)d_in[6];
    const float* Wo = (const float*)d_in[7];
    const float* bo = (const float*)d_in[8];
    const int* xlen = (const int*)d_in[9];
    float* out = (float*)d_out;

    cudaFuncSetAttribute(qkv_gemm_tc,
                         cudaFuncAttributeMaxDynamicSharedMemorySize,
                         GEMM_SMEM_BYTES);
    cudaFuncSetAttribute(out_gemm_tc,
                         cudaFuncAttributeMaxDynamicSharedMemorySize,
                         GEMM_SMEM_BYTES);
    cudaFuncSetAttribute(attn_kernel,
                         cudaFuncAttributeMaxDynamicSharedMemorySize,
                         ATTN_SMEM_BYTES);

    dim3 gqkv(DM_ / 128, (B_ * S_) / 128, 3);
    dim3 go(DM_ / 128, (B_ * S_) / 128);

    qkv_gemm_tc<<<gqkv, 256, GEMM_SMEM_BYTES>>>(x, Wq, bq, Wk, bk, Wv, bv);

    vmean_kernel<<<B_ * H_, 512>>>();

    attn_kernel<<<dim3(S_ / 64, H_, B_), 256, ATTN_SMEM_BYTES>>>(xlen);

    out_gemm_tc<<<go, 256, GEMM_SMEM_BYTES>>>(Wo, bo, out);
}